// round 4
// baseline (speedup 1.0000x reference)
#include <cuda_runtime.h>

#define D 1024
#define D4 (D / 4)
#define NB_SUM 512
#define LN_EPS 1e-5f

// Scratch (allocation-free)
__device__ float g_partial[D * NB_SUM];   // [col][block] transposed partials
__device__ float g_mean[D];
__device__ float g_global[D];
__device__ float g_v[D];
__device__ float g_attn[D];

// Software grid barrier state (re-zeroed by ln_kernel block 0 each run)
__device__ unsigned g_count = 0;
__device__ volatile unsigned g_release = 0;

__device__ __forceinline__ void grid_sync(unsigned phase, unsigned nblocks) {
    __syncthreads();
    if (threadIdx.x == 0) {
        __threadfence();
        unsigned prev = atomicAdd(&g_count, 1u);
        if (prev + 1u == phase * nblocks) {
            __threadfence();
            g_release = phase;
        } else {
            while (g_release < phase) __nanosleep(32);
        }
        __threadfence();
    }
    __syncthreads();
}

// ---------------------------------------------------------------------------
// Per-array branch-free partial column sum accumulation.
// ---------------------------------------------------------------------------
__device__ __forceinline__ void accum_array(const float* __restrict__ h, int n,
                                            int c4, float4& acc) {
    const int rpb = (n + NB_SUM - 1) / NB_SUM;
    const int r0 = blockIdx.x * rpb;
    const int r1 = min(r0 + rpb, n);
    const float4* base = reinterpret_cast<const float4*>(h) + c4;

    float4 a0 = make_float4(0,0,0,0), a1 = a0, a2 = a0, a3 = a0;
    int r = r0;
    for (; r + 4 <= r1; r += 4) {
        float4 v0 = __ldcs(base + (size_t)(r    ) * D4);
        float4 v1 = __ldcs(base + (size_t)(r + 1) * D4);
        float4 v2 = __ldcs(base + (size_t)(r + 2) * D4);
        float4 v3 = __ldcs(base + (size_t)(r + 3) * D4);
        a0.x += v0.x; a0.y += v0.y; a0.z += v0.z; a0.w += v0.w;
        a1.x += v1.x; a1.y += v1.y; a1.z += v1.z; a1.w += v1.w;
        a2.x += v2.x; a2.y += v2.y; a2.z += v2.z; a2.w += v2.w;
        a3.x += v3.x; a3.y += v3.y; a3.z += v3.z; a3.w += v3.w;
    }
    for (; r < r1; ++r) {
        float4 v = __ldcs(base + (size_t)r * D4);
        a0.x += v.x; a0.y += v.y; a0.z += v.z; a0.w += v.w;
    }
    acc.x += a0.x + a1.x + a2.x + a3.x;
    acc.y += a0.y + a1.y + a2.y + a3.y;
    acc.z += a0.z + a1.z + a2.z + a3.z;
    acc.w += a0.w + a1.w + a2.w + a3.w;
}

__device__ __forceinline__ void gemv_row(
        const float* __restrict__ W, const float* __restrict__ b,
        const float* __restrict__ x, float* __restrict__ y,
        int row, int tid, float* ws, float* out01) {
    const float4 w  = reinterpret_cast<const float4*>(W + (size_t)row * D)[tid];
    const float4 xx = reinterpret_cast<const float4*>(x)[tid];
    float s = w.x * xx.x + w.y * xx.y + w.z * xx.z + w.w * xx.w;
    #pragma unroll
    for (int o = 16; o > 0; o >>= 1) s += __shfl_xor_sync(0xFFFFFFFFu, s, o);
    if ((tid & 31) == 0) ws[tid >> 5] = s;
    __syncthreads();
    if (tid == 0) {
        float t = 0.f;
        #pragma unroll
        for (int w8 = 0; w8 < 8; ++w8) t += ws[w8];
        t += b[row];
        y[row] = t;
        if (out01) out01[row] = t;
    }
    __syncthreads();
}

__device__ __forceinline__ void reduce_col(int col, int tid, float* ws, float inv_total) {
    const float* p = g_partial + (size_t)col * NB_SUM;
    float s = p[tid] + p[tid + 256];
    #pragma unroll
    for (int o = 16; o > 0; o >>= 1) s += __shfl_xor_sync(0xFFFFFFFFu, s, o);
    if ((tid & 31) == 0) ws[tid >> 5] = s;
    __syncthreads();
    if (tid == 0) {
        float t = 0.f;
        #pragma unroll
        for (int w8 = 0; w8 < 8; ++w8) t += ws[w8];
        g_mean[col] = t * inv_total;
    }
    __syncthreads();
}

// ---------------------------------------------------------------------------
// Kernel 1 (mega): colsum partials -> [grid barrier] -> mean -> Wp -> Wv -> Wo
// 512 blocks x 256 threads, all co-resident (512 << 148*8).
// ---------------------------------------------------------------------------
__global__ void __launch_bounds__(256, 8) colsum_chain_kernel(
        const float* __restrict__ h0, const float* __restrict__ h1,
        const float* __restrict__ h2, const float* __restrict__ h3,
        int n0, int n1, int n2, int n3,
        const float* __restrict__ Wp, const float* __restrict__ bp,
        const float* __restrict__ Wv, const float* __restrict__ bv,
        const float* __restrict__ Wo, const float* __restrict__ bo,
        float* __restrict__ out) {
    const int tid = threadIdx.x;
    const int c4  = tid;
    __shared__ float ws[8];

    // Phase 0: streaming partial column sums (branch-free, per-array)
    float4 acc = make_float4(0,0,0,0);
    accum_array(h0, n0, c4, acc);
    accum_array(h1, n1, c4, acc);
    accum_array(h2, n2, c4, acc);
    accum_array(h3, n3, c4, acc);

    const int col = c4 * 4;
    g_partial[(size_t)(col + 0) * NB_SUM + blockIdx.x] = acc.x;
    g_partial[(size_t)(col + 1) * NB_SUM + blockIdx.x] = acc.y;
    g_partial[(size_t)(col + 2) * NB_SUM + blockIdx.x] = acc.z;
    g_partial[(size_t)(col + 3) * NB_SUM + blockIdx.x] = acc.w;

    const float inv_total = 1.f / (float)(n0 + n1 + n2 + n3);
    const int rA = blockIdx.x;          // rows/cols handled by this block
    const int rB = blockIdx.x + NB_SUM;

    grid_sync(1, NB_SUM);
    reduce_col(rA, tid, ws, inv_total);
    reduce_col(rB, tid, ws, inv_total);

    grid_sync(2, NB_SUM);
    gemv_row(Wp, bp, g_mean, g_global, rA, tid, ws, out);
    gemv_row(Wp, bp, g_mean, g_global, rB, tid, ws, out);

    grid_sync(3, NB_SUM);
    gemv_row(Wv, bv, g_global, g_v, rA, tid, ws, nullptr);
    gemv_row(Wv, bv, g_global, g_v, rB, tid, ws, nullptr);

    grid_sync(4, NB_SUM);
    gemv_row(Wo, bo, g_v, g_attn, rA, tid, ws, nullptr);
    gemv_row(Wo, bo, g_v, g_attn, rB, tid, ws, nullptr);
}

// ---------------------------------------------------------------------------
// Kernel 2: LayerNorm(h + attn). 128 threads per row (2 float4 per thread)
// -> low register pressure, high occupancy. 2 rows per 256-thread block.
// Block 0 also re-zeros the grid-barrier counters for the next graph replay.
// ---------------------------------------------------------------------------
__global__ void __launch_bounds__(256) ln_kernel(
        const float* __restrict__ h0, const float* __restrict__ h1,
        const float* __restrict__ h2, const float* __restrict__ h3,
        int n0, int n1, int n2, int n3,
        const float* __restrict__ gamma, const float* __restrict__ beta,
        float* __restrict__ out) {
    if (blockIdx.x == 0 && threadIdx.x == 0) {  // reset barrier for next replay
        g_count = 0;
        g_release = 0;
    }

    const int tid   = threadIdx.x;
    const int rin   = tid >> 7;          // row within block: 0/1
    const int t128  = tid & 127;         // lane within row group
    const int wrow  = t128 >> 5;         // warp within row: 0..3
    const int lane  = tid & 31;
    const int n01 = n0 + n1, n012 = n01 + n2;
    const int total = n012 + n3;
    const int g = blockIdx.x * 2 + rin;
    if (g >= total) return;

    const float* p; int rr;
    if (g < n0)        { p = h0; rr = g; }
    else if (g < n01)  { p = h1; rr = g - n0; }
    else if (g < n012) { p = h2; rr = g - n01; }
    else               { p = h3; rr = g - n012; }
    const float4* row  = reinterpret_cast<const float4*>(p + (size_t)rr * D);
    const float4* attn = reinterpret_cast<const float4*>(g_attn);

    // each thread: float4 indices t128 and t128+128
    float4 x0, x1;
    {
        float4 v = __ldcs(row + t128);
        float4 a = attn[t128];
        x0 = make_float4(v.x + a.x, v.y + a.y, v.z + a.z, v.w + a.w);
        v = __ldcs(row + t128 + 128);
        a = attn[t128 + 128];
        x1 = make_float4(v.x + a.x, v.y + a.y, v.z + a.z, v.w + a.w);
    }
    float sum = x0.x + x0.y + x0.z + x0.w + x1.x + x1.y + x1.z + x1.w;
    float sq  = x0.x*x0.x + x0.y*x0.y + x0.z*x0.z + x0.w*x0.w
              + x1.x*x1.x + x1.y*x1.y + x1.z*x1.z + x1.w*x1.w;
    #pragma unroll
    for (int o = 16; o > 0; o >>= 1) {
        sum += __shfl_xor_sync(0xFFFFFFFFu, sum, o);
        sq  += __shfl_xor_sync(0xFFFFFFFFu, sq,  o);
    }

    __shared__ float s_sum[2][4], s_sq[2][4];
    if (lane == 0) { s_sum[rin][wrow] = sum; s_sq[rin][wrow] = sq; }
    __syncthreads();
    sum = s_sum[rin][0] + s_sum[rin][1] + s_sum[rin][2] + s_sum[rin][3];
    sq  = s_sq[rin][0]  + s_sq[rin][1]  + s_sq[rin][2]  + s_sq[rin][3];

    const float inv_d = 1.f / (float)D;
    const float mean = sum * inv_d;
    const float var  = sq * inv_d - mean * mean;
    const float rstd = rsqrtf(var + LN_EPS);

    const float4* gm4 = reinterpret_cast<const float4*>(gamma);
    const float4* bt4 = reinterpret_cast<const float4*>(beta);
    float4* orow = reinterpret_cast<float4*>(out + D + (size_t)g * D);

    float4 gm = gm4[t128], bt = bt4[t128];
    float4 v;
    v.x = (x0.x - mean) * rstd * gm.x + bt.x;
    v.y = (x0.y - mean) * rstd * gm.y + bt.y;
    v.z = (x0.z - mean) * rstd * gm.z + bt.z;
    v.w = (x0.w - mean) * rstd * gm.w + bt.w;
    __stcs(orow + t128, v);

    gm = gm4[t128 + 128]; bt = bt4[t128 + 128];
    v.x = (x1.x - mean) * rstd * gm.x + bt.x;
    v.y = (x1.y - mean) * rstd * gm.y + bt.y;
    v.z = (x1.z - mean) * rstd * gm.z + bt.z;
    v.w = (x1.w - mean) * rstd * gm.w + bt.w;
    __stcs(orow + t128 + 128, v);
}

extern "C" void kernel_launch(void* const* d_in, const int* in_sizes, int n_in,
                              void* d_out, int out_size) {
    const float* h0    = (const float*)d_in[0];
    const float* h1    = (const float*)d_in[1];
    const float* h2    = (const float*)d_in[2];
    const float* h3    = (const float*)d_in[3];
    const float* Wp    = (const float*)d_in[4];
    const float* bp    = (const float*)d_in[5];
    const float* Wv    = (const float*)d_in[6];
    const float* bv    = (const float*)d_in[7];
    const float* Wo    = (const float*)d_in[8];
    const float* bo    = (const float*)d_in[9];
    const float* gamma = (const float*)d_in[10];
    const float* beta  = (const float*)d_in[11];
    float* out = (float*)d_out;

    const int n0 = in_sizes[0] / D;
    const int n1 = in_sizes[1] / D;
    const int n2 = in_sizes[2] / D;
    const int n3 = in_sizes[3] / D;
    const int total = n0 + n1 + n2 + n3;

    colsum_chain_kernel<<<NB_SUM, 256>>>(h0, h1, h2, h3, n0, n1, n2, n3,
                                         Wp, bp, Wv, bv, Wo, bo, out);
    const int ln_blocks = (total + 1) / 2;
    ln_kernel<<<ln_blocks, 256>>>(h0, h1, h2, h3, n0, n1, n2, n3, gamma, beta, out);
}

// round 8
// speedup vs baseline: 1.0405x; 1.0405x over previous
#include <cuda_runtime.h>

#define D 1024
#define D4 (D / 4)
#define NB_SUM 2048
#define LN_EPS 1e-5f

// Scratch (allocation-free)
__device__ float g_partial[D * NB_SUM];   // [col][block] transposed partials, 8 MB
__device__ float g_mean[D];
__device__ float g_global[D];
__device__ float g_v[D];
__device__ float g_attn[D];

// Software grid barrier state (re-zeroed by ln_kernel block 0 each run)
__device__ unsigned g_count = 0;
__device__ volatile unsigned g_release = 0;

__device__ __forceinline__ void grid_sync(unsigned phase, unsigned nblocks) {
    __syncthreads();
    if (threadIdx.x == 0) {
        __threadfence();
        unsigned prev = atomicAdd(&g_count, 1u);
        if (prev + 1u == phase * nblocks) {
            __threadfence();
            g_release = phase;
        } else {
            while (g_release < phase) __nanosleep(32);
        }
        __threadfence();
    }
    __syncthreads();
}

// ---------------------------------------------------------------------------
// Branch-free per-array partial column-sum accumulation.
// ---------------------------------------------------------------------------
__device__ __forceinline__ void accum_array(const float* __restrict__ h, int n,
                                            int c4, float4& acc) {
    const int rpb = (n + NB_SUM - 1) / NB_SUM;
    const int r0 = blockIdx.x * rpb;
    const int r1 = min(r0 + rpb, n);
    const float4* base = reinterpret_cast<const float4*>(h) + c4;

    float4 a0 = make_float4(0,0,0,0), a1 = a0, a2 = a0, a3 = a0;
    int r = r0;
    for (; r + 4 <= r1; r += 4) {
        float4 v0 = __ldcs(base + (size_t)(r    ) * D4);
        float4 v1 = __ldcs(base + (size_t)(r + 1) * D4);
        float4 v2 = __ldcs(base + (size_t)(r + 2) * D4);
        float4 v3 = __ldcs(base + (size_t)(r + 3) * D4);
        a0.x += v0.x; a0.y += v0.y; a0.z += v0.z; a0.w += v0.w;
        a1.x += v1.x; a1.y += v1.y; a1.z += v1.z; a1.w += v1.w;
        a2.x += v2.x; a2.y += v2.y; a2.z += v2.z; a2.w += v2.w;
        a3.x += v3.x; a3.y += v3.y; a3.z += v3.z; a3.w += v3.w;
    }
    for (; r < r1; ++r) {
        float4 v = __ldcs(base + (size_t)r * D4);
        a0.x += v.x; a0.y += v.y; a0.z += v.z; a0.w += v.w;
    }
    acc.x += a0.x + a1.x + a2.x + a3.x;
    acc.y += a0.y + a1.y + a2.y + a3.y;
    acc.z += a0.z + a1.z + a2.z + a3.z;
    acc.w += a0.w + a1.w + a2.w + a3.w;
}

// ---------------------------------------------------------------------------
// Kernel 1: streaming partial column sums. 2048 blocks -> full SM coverage.
// No launch_bounds reg cap: keep all accumulators + addresses in registers.
// ---------------------------------------------------------------------------
__global__ void colsum_kernel(
        const float* __restrict__ h0, const float* __restrict__ h1,
        const float* __restrict__ h2, const float* __restrict__ h3,
        int n0, int n1, int n2, int n3) {
    const int c4 = threadIdx.x;
    float4 acc = make_float4(0,0,0,0);
    accum_array(h0, n0, c4, acc);
    accum_array(h1, n1, c4, acc);
    accum_array(h2, n2, c4, acc);
    accum_array(h3, n3, c4, acc);

    const int col = c4 * 4;
    g_partial[(size_t)(col + 0) * NB_SUM + blockIdx.x] = acc.x;
    g_partial[(size_t)(col + 1) * NB_SUM + blockIdx.x] = acc.y;
    g_partial[(size_t)(col + 2) * NB_SUM + blockIdx.x] = acc.z;
    g_partial[(size_t)(col + 3) * NB_SUM + blockIdx.x] = acc.w;
}

// ---------------------------------------------------------------------------
// Kernel 2 (fused): reduce partials -> gemv(Wp) -> gemv(Wv) -> gemv(Wo).
// 1024 blocks x 256 threads, all co-resident (148*8 = 1184 >= 1024).
// ---------------------------------------------------------------------------
__device__ __forceinline__ void gemv_phase(
        const float* __restrict__ W, const float* __restrict__ b,
        const float* __restrict__ x, float* __restrict__ y,
        int row, int tid, float* ws, float* out01) {
    const float4 w  = reinterpret_cast<const float4*>(W + (size_t)row * D)[tid];
    const float4 xx = reinterpret_cast<const float4*>(x)[tid];
    float s = w.x * xx.x + w.y * xx.y + w.z * xx.z + w.w * xx.w;
    #pragma unroll
    for (int o = 16; o > 0; o >>= 1) s += __shfl_xor_sync(0xFFFFFFFFu, s, o);
    if ((tid & 31) == 0) ws[tid >> 5] = s;
    __syncthreads();
    if (tid == 0) {
        float t = 0.f;
        #pragma unroll
        for (int w8 = 0; w8 < 8; ++w8) t += ws[w8];
        t += b[row];
        y[row] = t;
        if (out01) out01[row] = t;
    }
}

__global__ void __launch_bounds__(256, 8) chain_kernel(
        const float* __restrict__ Wp, const float* __restrict__ bp,
        const float* __restrict__ Wv, const float* __restrict__ bv,
        const float* __restrict__ Wo, const float* __restrict__ bo,
        float* __restrict__ out, int total_rows) {
    const int row = blockIdx.x;       // 0..1023 (column for reduce, row for gemv)
    const int tid = threadIdx.x;
    __shared__ float ws[8];
    const unsigned nb = gridDim.x;

    // Phase A: reduce 2048 partials for this column -> mean
    {
        const float* p = g_partial + (size_t)row * NB_SUM;
        float s = 0.f;
        #pragma unroll
        for (int k = 0; k < NB_SUM / 256; ++k) s += p[tid + k * 256];
        #pragma unroll
        for (int o = 16; o > 0; o >>= 1) s += __shfl_xor_sync(0xFFFFFFFFu, s, o);
        if ((tid & 31) == 0) ws[tid >> 5] = s;
        __syncthreads();
        if (tid == 0) {
            float t = 0.f;
            #pragma unroll
            for (int w8 = 0; w8 < 8; ++w8) t += ws[w8];
            g_mean[row] = t / (float)total_rows;
        }
    }
    grid_sync(1, nb);
    gemv_phase(Wp, bp, g_mean,   g_global, row, tid, ws, out);
    grid_sync(2, nb);
    gemv_phase(Wv, bv, g_global, g_v,      row, tid, ws, nullptr);
    grid_sync(3, nb);
    gemv_phase(Wo, bo, g_v,      g_attn,   row, tid, ws, nullptr);
}

// ---------------------------------------------------------------------------
// Kernel 3: LayerNorm(h + attn). 128 threads per row, 2 rows / 256-thr block.
// Block 0 re-zeros the grid-barrier counters for the next graph replay.
// ---------------------------------------------------------------------------
__global__ void __launch_bounds__(256) ln_kernel(
        const float* __restrict__ h0, const float* __restrict__ h1,
        const float* __restrict__ h2, const float* __restrict__ h3,
        int n0, int n1, int n2, int n3,
        const float* __restrict__ gamma, const float* __restrict__ beta,
        float* __restrict__ out) {
    if (blockIdx.x == 0 && threadIdx.x == 0) {  // reset barrier for next replay
        g_count = 0;
        g_release = 0;
    }

    const int tid   = threadIdx.x;
    const int rin   = tid >> 7;          // row within block: 0/1
    const int t128  = tid & 127;
    const int wrow  = t128 >> 5;
    const int lane  = tid & 31;
    const int n01 = n0 + n1, n012 = n01 + n2;
    const int total = n012 + n3;
    const int g = blockIdx.x * 2 + rin;
    if (g >= total) return;

    const float* p; int rr;
    if (g < n0)        { p = h0; rr = g; }
    else if (g < n01)  { p = h1; rr = g - n0; }
    else if (g < n012) { p = h2; rr = g - n01; }
    else               { p = h3; rr = g - n012; }
    const float4* row  = reinterpret_cast<const float4*>(p + (size_t)rr * D);
    const float4* attn = reinterpret_cast<const float4*>(g_attn);

    float4 x0, x1;
    {
        float4 v = __ldcs(row + t128);
        float4 a = attn[t128];
        x0 = make_float4(v.x + a.x, v.y + a.y, v.z + a.z, v.w + a.w);
        v = __ldcs(row + t128 + 128);
        a = attn[t128 + 128];
        x1 = make_float4(v.x + a.x, v.y + a.y, v.z + a.z, v.w + a.w);
    }
    float sum = x0.x + x0.y + x0.z + x0.w + x1.x + x1.y + x1.z + x1.w;
    float sq  = x0.x*x0.x + x0.y*x0.y + x0.z*x0.z + x0.w*x0.w
              + x1.x*x1.x + x1.y*x1.y + x1.z*x1.z + x1.w*x1.w;
    #pragma unroll
    for (int o = 16; o > 0; o >>= 1) {
        sum += __shfl_xor_sync(0xFFFFFFFFu, sum, o);
        sq  += __shfl_xor_sync(0xFFFFFFFFu, sq,  o);
    }

    __shared__ float s_sum[2][4], s_sq[2][4];
    if (lane == 0) { s_sum[rin][wrow] = sum; s_sq[rin][wrow] = sq; }
    __syncthreads();
    sum = s_sum[rin][0] + s_sum[rin][1] + s_sum[rin][2] + s_sum[rin][3];
    sq  = s_sq[rin][0]  + s_sq[rin][1]  + s_sq[rin][2]  + s_sq[rin][3];

    const float inv_d = 1.f / (float)D;
    const float mean = sum * inv_d;
    const float var  = sq * inv_d - mean * mean;
    const float rstd = rsqrtf(var + LN_EPS);

    const float4* gm4 = reinterpret_cast<const float4*>(gamma);
    const float4* bt4 = reinterpret_cast<const float4*>(beta);
    float4* orow = reinterpret_cast<float4*>(out + D + (size_t)g * D);

    float4 gm = gm4[t128], bt = bt4[t128];
    float4 v;
    v.x = (x0.x - mean) * rstd * gm.x + bt.x;
    v.y = (x0.y - mean) * rstd * gm.y + bt.y;
    v.z = (x0.z - mean) * rstd * gm.z + bt.z;
    v.w = (x0.w - mean) * rstd * gm.w + bt.w;
    __stcs(orow + t128, v);

    gm = gm4[t128 + 128]; bt = bt4[t128 + 128];
    v.x = (x1.x - mean) * rstd * gm.x + bt.x;
    v.y = (x1.y - mean) * rstd * gm.y + bt.y;
    v.z = (x1.z - mean) * rstd * gm.z + bt.z;
    v.w = (x1.w - mean) * rstd * gm.w + bt.w;
    __stcs(orow + t128 + 128, v);
}

extern "C" void kernel_launch(void* const* d_in, const int* in_sizes, int n_in,
                              void* d_out, int out_size) {
    const float* h0    = (const float*)d_in[0];
    const float* h1    = (const float*)d_in[1];
    const float* h2    = (const float*)d_in[2];
    const float* h3    = (const float*)d_in[3];
    const float* Wp    = (const float*)d_in[4];
    const float* bp    = (const float*)d_in[5];
    const float* Wv    = (const float*)d_in[6];
    const float* bv    = (const float*)d_in[7];
    const float* Wo    = (const float*)d_in[8];
    const float* bo    = (const float*)d_in[9];
    const float* gamma = (const float*)d_in[10];
    const float* beta  = (const float*)d_in[11];
    float* out = (float*)d_out;

    const int n0 = in_sizes[0] / D;
    const int n1 = in_sizes[1] / D;
    const int n2 = in_sizes[2] / D;
    const int n3 = in_sizes[3] / D;
    const int total = n0 + n1 + n2 + n3;

    colsum_kernel<<<NB_SUM, 256>>>(h0, h1, h2, h3, n0, n1, n2, n3);
    chain_kernel<<<D, 256>>>(Wp, bp, Wv, bv, Wo, bo, out, total);
    const int ln_blocks = (total + 1) / 2;
    ln_kernel<<<ln_blocks, 256>>>(h0, h1, h2, h3, n0, n1, n2, n3, gamma, beta, out);
}

// round 10
// speedup vs baseline: 1.0482x; 1.0074x over previous
#include <cuda_runtime.h>

#define D 1024
#define D4 (D / 4)
#define NBLK 888              // 148 SMs x 6 blocks: exactly one resident wave
#define LN_EPS 1e-5f

// Scratch (allocation-free)
__device__ float g_partial[D * NBLK];   // [col][block] transposed partials
__device__ float g_mean[D];
__device__ float g_global[D];
__device__ float g_v[D];
__device__ float g_attn[D];

// Software grid barrier state (re-zeroed by ln_kernel block 0 each run)
__device__ unsigned g_count = 0;
__device__ volatile unsigned g_release = 0;

__device__ __forceinline__ void grid_sync(unsigned phase) {
    __syncthreads();
    if (threadIdx.x == 0) {
        __threadfence();
        unsigned prev = atomicAdd(&g_count, 1u);
        if (prev + 1u == phase * (unsigned)NBLK) {
            __threadfence();
            g_release = phase;
        } else {
            while (g_release < phase) __nanosleep(32);
        }
        __threadfence();
    }
    __syncthreads();
}

// ---------------------------------------------------------------------------
// Branch-free contiguous-range column-sum accumulation (rows [lo, hi) of h).
// ---------------------------------------------------------------------------
__device__ __forceinline__ void accum_range(const float* __restrict__ h,
                                            int lo, int hi, int c4, float4& acc) {
    if (lo >= hi) return;
    const float4* base = reinterpret_cast<const float4*>(h) + c4;
    float4 a0 = make_float4(0,0,0,0), a1 = a0, a2 = a0, a3 = a0;
    int r = lo;
    for (; r + 4 <= hi; r += 4) {
        float4 v0 = __ldcs(base + (size_t)(r    ) * D4);
        float4 v1 = __ldcs(base + (size_t)(r + 1) * D4);
        float4 v2 = __ldcs(base + (size_t)(r + 2) * D4);
        float4 v3 = __ldcs(base + (size_t)(r + 3) * D4);
        a0.x += v0.x; a0.y += v0.y; a0.z += v0.z; a0.w += v0.w;
        a1.x += v1.x; a1.y += v1.y; a1.z += v1.z; a1.w += v1.w;
        a2.x += v2.x; a2.y += v2.y; a2.z += v2.z; a2.w += v2.w;
        a3.x += v3.x; a3.y += v3.y; a3.z += v3.z; a3.w += v3.w;
    }
    for (; r < hi; ++r) {
        float4 v = __ldcs(base + (size_t)r * D4);
        a0.x += v.x; a0.y += v.y; a0.z += v.z; a0.w += v.w;
    }
    acc.x += a0.x + a1.x + a2.x + a3.x;
    acc.y += a0.y + a1.y + a2.y + a3.y;
    acc.z += a0.z + a1.z + a2.z + a3.z;
    acc.w += a0.w + a1.w + a2.w + a3.w;
}

__device__ __forceinline__ void reduce_col(int col, int tid, float* ws, float inv_total) {
    const float* p = g_partial + (size_t)col * NBLK;
    float s = 0.f;
    for (int i = tid; i < NBLK; i += 256) s += p[i];
    #pragma unroll
    for (int o = 16; o > 0; o >>= 1) s += __shfl_xor_sync(0xFFFFFFFFu, s, o);
    if ((tid & 31) == 0) ws[tid >> 5] = s;
    __syncthreads();
    if (tid == 0) {
        float t = 0.f;
        #pragma unroll
        for (int w8 = 0; w8 < 8; ++w8) t += ws[w8];
        g_mean[col] = t * inv_total;
    }
    __syncthreads();
}

__device__ __forceinline__ void gemv_row(
        const float* __restrict__ W, const float* __restrict__ b,
        const float* __restrict__ x, float* __restrict__ y,
        int row, int tid, float* ws, float* out01) {
    const float4 w  = reinterpret_cast<const float4*>(W + (size_t)row * D)[tid];
    const float4 xx = reinterpret_cast<const float4*>(x)[tid];
    float s = w.x * xx.x + w.y * xx.y + w.z * xx.z + w.w * xx.w;
    #pragma unroll
    for (int o = 16; o > 0; o >>= 1) s += __shfl_xor_sync(0xFFFFFFFFu, s, o);
    if ((tid & 31) == 0) ws[tid >> 5] = s;
    __syncthreads();
    if (tid == 0) {
        float t = 0.f;
        #pragma unroll
        for (int w8 = 0; w8 < 8; ++w8) t += ws[w8];
        t += b[row];
        y[row] = t;
        if (out01) out01[row] = t;
    }
    __syncthreads();
}

// ---------------------------------------------------------------------------
// Mega-kernel: colsum partials -> mean -> gemv(Wp) -> gemv(Wv) -> gemv(Wo).
// 888 blocks x 256 threads = exactly one co-resident wave (6 blocks/SM),
// so the software grid barrier is deadlock-free and there is no wave tail.
// ---------------------------------------------------------------------------
__global__ void __launch_bounds__(256, 6) colsum_chain_kernel(
        const float* __restrict__ h0, const float* __restrict__ h1,
        const float* __restrict__ h2, const float* __restrict__ h3,
        int n0, int n1, int n2, int n3,
        const float* __restrict__ Wp, const float* __restrict__ bp,
        const float* __restrict__ Wv, const float* __restrict__ bv,
        const float* __restrict__ Wo, const float* __restrict__ bo,
        float* __restrict__ out) {
    const int tid = threadIdx.x;
    const int c4  = tid;
    const int b   = blockIdx.x;
    __shared__ float ws[8];

    const int s1 = n0, s2 = n0 + n1, s3 = s2 + n2;
    const int total = s3 + n3;

    // Flat global-row chunking: block b owns rows [gb, ge) of the virtual
    // concat; the range intersects at most 2 arrays -> contiguous sub-loops.
    const int rpb = (total + NBLK - 1) / NBLK;
    const int gb = b * rpb;
    const int ge = min(gb + rpb, total);

    float4 acc = make_float4(0,0,0,0);
    if (gb < ge) {
        accum_range(h0, max(gb, 0)       , min(ge, n0)       , c4, acc);
        accum_range(h1, max(gb - s1, 0)  , min(ge - s1, n1)  , c4, acc);
        accum_range(h2, max(gb - s2, 0)  , min(ge - s2, n2)  , c4, acc);
        accum_range(h3, max(gb - s3, 0)  , min(ge - s3, n3)  , c4, acc);
    }

    const int col = c4 * 4;
    g_partial[(size_t)(col + 0) * NBLK + b] = acc.x;
    g_partial[(size_t)(col + 1) * NBLK + b] = acc.y;
    g_partial[(size_t)(col + 2) * NBLK + b] = acc.z;
    g_partial[(size_t)(col + 3) * NBLK + b] = acc.w;

    const float inv_total = 1.f / (float)total;
    const int rA = b;                 // always < 1024
    const int rB = b + NBLK;          // valid when b < 1024 - NBLK (=136)
    const bool hasB = (rB < D);

    grid_sync(1);
    reduce_col(rA, tid, ws, inv_total);
    if (hasB) reduce_col(rB, tid, ws, inv_total);

    grid_sync(2);
    gemv_row(Wp, bp, g_mean, g_global, rA, tid, ws, out);
    if (hasB) gemv_row(Wp, bp, g_mean, g_global, rB, tid, ws, out);

    grid_sync(3);
    gemv_row(Wv, bv, g_global, g_v, rA, tid, ws, nullptr);
    if (hasB) gemv_row(Wv, bv, g_global, g_v, rB, tid, ws, nullptr);

    grid_sync(4);
    gemv_row(Wo, bo, g_v, g_attn, rA, tid, ws, nullptr);
    if (hasB) gemv_row(Wo, bo, g_v, g_attn, rB, tid, ws, nullptr);
}

// ---------------------------------------------------------------------------
// LayerNorm(h + attn). 128 threads per row, 2 rows / 256-thr block.
// Block 0 re-zeros the grid-barrier counters for the next graph replay.
// ---------------------------------------------------------------------------
__global__ void __launch_bounds__(256) ln_kernel(
        const float* __restrict__ h0, const float* __restrict__ h1,
        const float* __restrict__ h2, const float* __restrict__ h3,
        int n0, int n1, int n2, int n3,
        const float* __restrict__ gamma, const float* __restrict__ beta,
        float* __restrict__ out) {
    if (blockIdx.x == 0 && threadIdx.x == 0) {  // reset barrier for next replay
        g_count = 0;
        g_release = 0;
    }

    const int tid   = threadIdx.x;
    const int rin   = tid >> 7;          // row within block: 0/1
    const int t128  = tid & 127;
    const int wrow  = t128 >> 5;
    const int lane  = tid & 31;
    const int n01 = n0 + n1, n012 = n01 + n2;
    const int total = n012 + n3;
    const int g = blockIdx.x * 2 + rin;
    if (g >= total) return;

    const float* p; int rr;
    if (g < n0)        { p = h0; rr = g; }
    else if (g < n01)  { p = h1; rr = g - n0; }
    else if (g < n012) { p = h2; rr = g - n01; }
    else               { p = h3; rr = g - n012; }
    const float4* row  = reinterpret_cast<const float4*>(p + (size_t)rr * D);
    const float4* attn = reinterpret_cast<const float4*>(g_attn);

    float4 x0, x1;
    {
        float4 v = __ldcs(row + t128);
        float4 a = attn[t128];
        x0 = make_float4(v.x + a.x, v.y + a.y, v.z + a.z, v.w + a.w);
        v = __ldcs(row + t128 + 128);
        a = attn[t128 + 128];
        x1 = make_float4(v.x + a.x, v.y + a.y, v.z + a.z, v.w + a.w);
    }
    float sum = x0.x + x0.y + x0.z + x0.w + x1.x + x1.y + x1.z + x1.w;
    float sq  = x0.x*x0.x + x0.y*x0.y + x0.z*x0.z + x0.w*x0.w
              + x1.x*x1.x + x1.y*x1.y + x1.z*x1.z + x1.w*x1.w;
    #pragma unroll
    for (int o = 16; o > 0; o >>= 1) {
        sum += __shfl_xor_sync(0xFFFFFFFFu, sum, o);
        sq  += __shfl_xor_sync(0xFFFFFFFFu, sq,  o);
    }

    __shared__ float s_sum[2][4], s_sq[2][4];
    if (lane == 0) { s_sum[rin][wrow] = sum; s_sq[rin][wrow] = sq; }
    __syncthreads();
    sum = s_sum[rin][0] + s_sum[rin][1] + s_sum[rin][2] + s_sum[rin][3];
    sq  = s_sq[rin][0]  + s_sq[rin][1]  + s_sq[rin][2]  + s_sq[rin][3];

    const float inv_d = 1.f / (float)D;
    const float mean = sum * inv_d;
    const float var  = sq * inv_d - mean * mean;
    const float rstd = rsqrtf(var + LN_EPS);

    const float4* gm4 = reinterpret_cast<const float4*>(gamma);
    const float4* bt4 = reinterpret_cast<const float4*>(beta);
    float4* orow = reinterpret_cast<float4*>(out + D + (size_t)g * D);

    float4 gm = gm4[t128], bt = bt4[t128];
    float4 v;
    v.x = (x0.x - mean) * rstd * gm.x + bt.x;
    v.y = (x0.y - mean) * rstd * gm.y + bt.y;
    v.z = (x0.z - mean) * rstd * gm.z + bt.z;
    v.w = (x0.w - mean) * rstd * gm.w + bt.w;
    __stcs(orow + t128, v);

    gm = gm4[t128 + 128]; bt = bt4[t128 + 128];
    v.x = (x1.x - mean) * rstd * gm.x + bt.x;
    v.y = (x1.y - mean) * rstd * gm.y + bt.y;
    v.z = (x1.z - mean) * rstd * gm.z + bt.z;
    v.w = (x1.w - mean) * rstd * gm.w + bt.w;
    __stcs(orow + t128 + 128, v);
}

extern "C" void kernel_launch(void* const* d_in, const int* in_sizes, int n_in,
                              void* d_out, int out_size) {
    const float* h0    = (const float*)d_in[0];
    const float* h1    = (const float*)d_in[1];
    const float* h2    = (const float*)d_in[2];
    const float* h3    = (const float*)d_in[3];
    const float* Wp    = (const float*)d_in[4];
    const float* bp    = (const float*)d_in[5];
    const float* Wv    = (const float*)d_in[6];
    const float* bv    = (const float*)d_in[7];
    const float* Wo    = (const float*)d_in[8];
    const float* bo    = (const float*)d_in[9];
    const float* gamma = (const float*)d_in[10];
    const float* beta  = (const float*)d_in[11];
    float* out = (float*)d_out;

    const int n0 = in_sizes[0] / D;
    const int n1 = in_sizes[1] / D;
    const int n2 = in_sizes[2] / D;
    const int n3 = in_sizes[3] / D;
    const int total = n0 + n1 + n2 + n3;

    colsum_chain_kernel<<<NBLK, 256>>>(h0, h1, h2, h3, n0, n1, n2, n3,
                                       Wp, bp, Wv, bv, Wo, bo, out);
    const int ln_blocks = (total + 1) / 2;
    ln_kernel<<<ln_blocks, 256>>>(h0, h1, h2, h3, n0, n1, n2, n3, gamma, beta, out);
}

// round 15
// speedup vs baseline: 1.0518x; 1.0034x over previous
#include <cuda_runtime.h>

#define D 1024
#define D4 (D / 4)
#define NBLK 888              // 148 SMs x 6 blocks: exactly one resident wave
#define LN_EPS 1e-5f

// Scratch (allocation-free)
__device__ float g_partial[D * NBLK];   // [col][block] transposed partials
__device__ float g_mean[D];
__device__ float g_global[D];
__device__ float g_v[D];
__device__ float g_attn[D];

// Software grid barrier state (re-zeroed by ln_kernel block 0 each run)
__device__ unsigned g_count = 0;
__device__ volatile unsigned g_release = 0;

__device__ __forceinline__ void grid_sync(unsigned phase) {
    __syncthreads();
    if (threadIdx.x == 0) {
        __threadfence();
        unsigned prev = atomicAdd(&g_count, 1u);
        if (prev + 1u == phase * (unsigned)NBLK) {
            __threadfence();
            g_release = phase;
        } else {
            while (g_release < phase) __nanosleep(16);
        }
        __threadfence();
    }
    __syncthreads();
}

__device__ __forceinline__ void l2_prefetch(const void* p) {
    asm volatile("prefetch.global.L2 [%0];" :: "l"(p));
}

// ---------------------------------------------------------------------------
// Branch-free contiguous-range column-sum accumulation (rows [lo, hi) of h).
// ---------------------------------------------------------------------------
__device__ __forceinline__ void accum_range(const float* __restrict__ h,
                                            int lo, int hi, int c4, float4& acc) {
    if (lo >= hi) return;
    const float4* base = reinterpret_cast<const float4*>(h) + c4;
    float4 a0 = make_float4(0,0,0,0), a1 = a0, a2 = a0, a3 = a0;
    int r = lo;
    for (; r + 4 <= hi; r += 4) {
        float4 v0 = __ldcs(base + (size_t)(r    ) * D4);
        float4 v1 = __ldcs(base + (size_t)(r + 1) * D4);
        float4 v2 = __ldcs(base + (size_t)(r + 2) * D4);
        float4 v3 = __ldcs(base + (size_t)(r + 3) * D4);
        a0.x += v0.x; a0.y += v0.y; a0.z += v0.z; a0.w += v0.w;
        a1.x += v1.x; a1.y += v1.y; a1.z += v1.z; a1.w += v1.w;
        a2.x += v2.x; a2.y += v2.y; a2.z += v2.z; a2.w += v2.w;
        a3.x += v3.x; a3.y += v3.y; a3.z += v3.z; a3.w += v3.w;
    }
    for (; r < hi; ++r) {
        float4 v = __ldcs(base + (size_t)r * D4);
        a0.x += v.x; a0.y += v.y; a0.z += v.z; a0.w += v.w;
    }
    acc.x += a0.x + a1.x + a2.x + a3.x;
    acc.y += a0.y + a1.y + a2.y + a3.y;
    acc.z += a0.z + a1.z + a2.z + a3.z;
    acc.w += a0.w + a1.w + a2.w + a3.w;
}

__device__ __forceinline__ void reduce_col(int col, int tid, float* ws, float inv_total) {
    const float* p = g_partial + (size_t)col * NBLK;
    float s = 0.f;
    for (int i = tid; i < NBLK; i += 256) s += p[i];
    #pragma unroll
    for (int o = 16; o > 0; o >>= 1) s += __shfl_xor_sync(0xFFFFFFFFu, s, o);
    if ((tid & 31) == 0) ws[tid >> 5] = s;
    __syncthreads();
    if (tid == 0) {
        float t = 0.f;
        #pragma unroll
        for (int w8 = 0; w8 < 8; ++w8) t += ws[w8];
        g_mean[col] = t * inv_total;
    }
    __syncthreads();
}

__device__ __forceinline__ void gemv_row(
        const float* __restrict__ W, const float* __restrict__ b,
        const float* __restrict__ x, float* __restrict__ y,
        int row, int tid, float* ws, float* out01) {
    const float4 w  = reinterpret_cast<const float4*>(W + (size_t)row * D)[tid];
    const float4 xx = reinterpret_cast<const float4*>(x)[tid];
    float s = w.x * xx.x + w.y * xx.y + w.z * xx.z + w.w * xx.w;
    #pragma unroll
    for (int o = 16; o > 0; o >>= 1) s += __shfl_xor_sync(0xFFFFFFFFu, s, o);
    if ((tid & 31) == 0) ws[tid >> 5] = s;
    __syncthreads();
    if (tid == 0) {
        float t = 0.f;
        #pragma unroll
        for (int w8 = 0; w8 < 8; ++w8) t += ws[w8];
        t += b[row];
        y[row] = t;
        if (out01) out01[row] = t;
    }
    __syncthreads();
}

// ---------------------------------------------------------------------------
// Mega-kernel: [prefetch W to L2] colsum partials -> mean -> Wp -> Wv -> Wo.
// 888 blocks x 256 threads = exactly one co-resident wave (6 blocks/SM).
// ---------------------------------------------------------------------------
__global__ void __launch_bounds__(256, 6) colsum_chain_kernel(
        const float* __restrict__ h0, const float* __restrict__ h1,
        const float* __restrict__ h2, const float* __restrict__ h3,
        int n0, int n1, int n2, int n3,
        const float* __restrict__ Wp, const float* __restrict__ bp,
        const float* __restrict__ Wv, const float* __restrict__ bv,
        const float* __restrict__ Wo, const float* __restrict__ bo,
        float* __restrict__ out) {
    const int tid = threadIdx.x;
    const int c4  = tid;
    const int b   = blockIdx.x;
    __shared__ float ws[8];

    // ---- Async L2 prefetch of the three 4MB weight matrices (this block's
    // slice), so the GEMV phases hit L2 instead of cold DRAM. ----
    {
        const size_t MAT_BYTES = (size_t)D * D * sizeof(float);
        size_t lo = (MAT_BYTES * (size_t)b) / NBLK & ~(size_t)127;
        size_t hi = (MAT_BYTES * (size_t)(b + 1)) / NBLK;
        const char* cp = (const char*)Wp;
        const char* cv = (const char*)Wv;
        const char* co = (const char*)Wo;
        for (size_t off = lo + (size_t)tid * 128; off < hi; off += 256 * 128) {
            l2_prefetch(cp + off);
            l2_prefetch(cv + off);
            l2_prefetch(co + off);
        }
    }

    const int s1 = n0, s2 = n0 + n1, s3 = s2 + n2;
    const int total = s3 + n3;

    // Flat global-row chunking: block b owns rows [gb, ge) of the virtual
    // concat; the range intersects at most 2 arrays -> contiguous sub-loops.
    const int rpb = (total + NBLK - 1) / NBLK;
    const int gb = b * rpb;
    const int ge = min(gb + rpb, total);

    float4 acc = make_float4(0,0,0,0);
    if (gb < ge) {
        accum_range(h0, max(gb, 0)       , min(ge, n0)       , c4, acc);
        accum_range(h1, max(gb - s1, 0)  , min(ge - s1, n1)  , c4, acc);
        accum_range(h2, max(gb - s2, 0)  , min(ge - s2, n2)  , c4, acc);
        accum_range(h3, max(gb - s3, 0)  , min(ge - s3, n3)  , c4, acc);
    }

    const int col = c4 * 4;
    g_partial[(size_t)(col + 0) * NBLK + b] = acc.x;
    g_partial[(size_t)(col + 1) * NBLK + b] = acc.y;
    g_partial[(size_t)(col + 2) * NBLK + b] = acc.z;
    g_partial[(size_t)(col + 3) * NBLK + b] = acc.w;

    const float inv_total = 1.f / (float)total;
    const int rA = b;                 // always < 1024
    const int rB = b + NBLK;          // valid when b < 1024 - NBLK (=136)
    const bool hasB = (rB < D);

    grid_sync(1);
    reduce_col(rA, tid, ws, inv_total);
    if (hasB) reduce_col(rB, tid, ws, inv_total);

    grid_sync(2);
    gemv_row(Wp, bp, g_mean, g_global, rA, tid, ws, out);
    if (hasB) gemv_row(Wp, bp, g_mean, g_global, rB, tid, ws, out);

    grid_sync(3);
    gemv_row(Wv, bv, g_global, g_v, rA, tid, ws, nullptr);
    if (hasB) gemv_row(Wv, bv, g_global, g_v, rB, tid, ws, nullptr);

    grid_sync(4);
    gemv_row(Wo, bo, g_v, g_attn, rA, tid, ws, nullptr);
    if (hasB) gemv_row(Wo, bo, g_v, g_attn, rB, tid, ws, nullptr);
}

// ---------------------------------------------------------------------------
// LayerNorm(h + attn). 128 threads per row, 2 rows / 256-thr block.
// Block 0 re-zeros the grid-barrier counters for the next graph replay.
// ---------------------------------------------------------------------------
__global__ void __launch_bounds__(256) ln_kernel(
        const float* __restrict__ h0, const float* __restrict__ h1,
        const float* __restrict__ h2, const float* __restrict__ h3,
        int n0, int n1, int n2, int n3,
        const float* __restrict__ gamma, const float* __restrict__ beta,
        float* __restrict__ out) {
    if (blockIdx.x == 0 && threadIdx.x == 0) {  // reset barrier for next replay
        g_count = 0;
        g_release = 0;
    }

    const int tid   = threadIdx.x;
    const int rin   = tid >> 7;          // row within block: 0/1
    const int t128  = tid & 127;
    const int wrow  = t128 >> 5;
    const int lane  = tid & 31;
    const int n01 = n0 + n1, n012 = n01 + n2;
    const int total = n012 + n3;
    const int g = blockIdx.x * 2 + rin;
    if (g >= total) return;

    const float* p; int rr;
    if (g < n0)        { p = h0; rr = g; }
    else if (g < n01)  { p = h1; rr = g - n0; }
    else if (g < n012) { p = h2; rr = g - n01; }
    else               { p = h3; rr = g - n012; }
    const float4* row  = reinterpret_cast<const float4*>(p + (size_t)rr * D);
    const float4* attn = reinterpret_cast<const float4*>(g_attn);

    float4 x0, x1;
    {
        float4 v = __ldcs(row + t128);
        float4 a = attn[t128];
        x0 = make_float4(v.x + a.x, v.y + a.y, v.z + a.z, v.w + a.w);
        v = __ldcs(row + t128 + 128);
        a = attn[t128 + 128];
        x1 = make_float4(v.x + a.x, v.y + a.y, v.z + a.z, v.w + a.w);
    }
    float sum = x0.x + x0.y + x0.z + x0.w + x1.x + x1.y + x1.z + x1.w;
    float sq  = x0.x*x0.x + x0.y*x0.y + x0.z*x0.z + x0.w*x0.w
              + x1.x*x1.x + x1.y*x1.y + x1.z*x1.z + x1.w*x1.w;
    #pragma unroll
    for (int o = 16; o > 0; o >>= 1) {
        sum += __shfl_xor_sync(0xFFFFFFFFu, sum, o);
        sq  += __shfl_xor_sync(0xFFFFFFFFu, sq,  o);
    }

    __shared__ float s_sum[2][4], s_sq[2][4];
    if (lane == 0) { s_sum[rin][wrow] = sum; s_sq[rin][wrow] = sq; }
    __syncthreads();
    sum = s_sum[rin][0] + s_sum[rin][1] + s_sum[rin][2] + s_sum[rin][3];
    sq  = s_sq[rin][0]  + s_sq[rin][1]  + s_sq[rin][2]  + s_sq[rin][3];

    const float inv_d = 1.f / (float)D;
    const float mean = sum * inv_d;
    const float var  = sq * inv_d - mean * mean;
    const float rstd = rsqrtf(var + LN_EPS);

    const float4* gm4 = reinterpret_cast<const float4*>(gamma);
    const float4* bt4 = reinterpret_cast<const float4*>(beta);
    float4* orow = reinterpret_cast<float4*>(out + D + (size_t)g * D);

    float4 gm = gm4[t128], bt = bt4[t128];
    float4 v;
    v.x = (x0.x - mean) * rstd * gm.x + bt.x;
    v.y = (x0.y - mean) * rstd * gm.y + bt.y;
    v.z = (x0.z - mean) * rstd * gm.z + bt.z;
    v.w = (x0.w - mean) * rstd * gm.w + bt.w;
    __stcs(orow + t128, v);

    gm = gm4[t128 + 128]; bt = bt4[t128 + 128];
    v.x = (x1.x - mean) * rstd * gm.x + bt.x;
    v.y = (x1.y - mean) * rstd * gm.y + bt.y;
    v.z = (x1.z - mean) * rstd * gm.z + bt.z;
    v.w = (x1.w - mean) * rstd * gm.w + bt.w;
    __stcs(orow + t128 + 128, v);
}

extern "C" void kernel_launch(void* const* d_in, const int* in_sizes, int n_in,
                              void* d_out, int out_size) {
    const float* h0    = (const float*)d_in[0];
    const float* h1    = (const float*)d_in[1];
    const float* h2    = (const float*)d_in[2];
    const float* h3    = (const float*)d_in[3];
    const float* Wp    = (const float*)d_in[4];
    const float* bp    = (const float*)d_in[5];
    const float* Wv    = (const float*)d_in[6];
    const float* bv    = (const float*)d_in[7];
    const float* Wo    = (const float*)d_in[8];
    const float* bo    = (const float*)d_in[9];
    const float* gamma = (const float*)d_in[10];
    const float* beta  = (const float*)d_in[11];
    float* out = (float*)d_out;

    const int n0 = in_sizes[0] / D;
    const int n1 = in_sizes[1] / D;
    const int n2 = in_sizes[2] / D;
    const int n3 = in_sizes[3] / D;
    const int total = n0 + n1 + n2 + n3;

    colsum_chain_kernel<<<NBLK, 256>>>(h0, h1, h2, h3, n0, n1, n2, n3,
                                       Wp, bp, Wv, bv, Wo, bo, out);
    const int ln_blocks = (total + 1) / 2;
    ln_kernel<<<ln_blocks, 256>>>(h0, h1, h2, h3, n0, n1, n2, n3, gamma, beta, out);
}